// round 17
// baseline (speedup 1.0000x reference)
#include <cuda_runtime.h>
#include <cstdint>

constexpr int K  = 4096;
constexpr int N  = 11008;
constexpr int NW = N / 8;        // qzeros columns = 1376
constexpr int WR = K / 8;        // packed weight rows = 512
constexpr int WR2 = WR / 2;      // row-pairs = 256
constexpr int N4 = N / 4;        // float4 columns = 2752

// nib + 2^23, exact in fp32. (w+M) - (z+M) == w - z exactly for 0..15.
#define MAGIC 0x4B000000u

__device__ __forceinline__ float nib2f(unsigned word, int sh) {
    return __uint_as_float(((word >> sh) & 15u) | MAGIC);
}

__global__ __launch_bounds__(256) void dequant_kernel(
    const int*   __restrict__ qweight,  // [K/8, N]
    const int*   __restrict__ qzeros,   // [G, N/8]
    const float* __restrict__ scales,   // [G, N]
    const int*   __restrict__ g_idx,    // [K]
    float*       __restrict__ out)      // [K, N]
{
    const int n4 = blockIdx.x * blockDim.x + threadIdx.x;  // over N/4
    const int wp = blockIdx.y;                             // row-pair 0..255
    if (n4 >= N4) return;
    const int n  = n4 * 4;
    const int wr = wp * 2;      // first packed row of the pair

    // two packed word-rows, SAME 4 columns: both LDG.128 fully coalesced
    // across the warp and front-batched -> MLP_p1 = 2.
    const uint4 qwa = *reinterpret_cast<const uint4*>(qweight + (size_t)wr * N + n);
    const uint4 qwb = *reinterpret_cast<const uint4*>(qweight + (size_t)(wr + 1) * N + n);

    const int zsh = (n & 4) << 2;   // 0 or 16
    const int nz  = n >> 3;         // qzeros column

    // 16 k-rows: one group unless a boundary falls inside (<=31 of 256 pairs)
    const int g0  = __ldg(g_idx + wr * 8);
    const int g15 = __ldg(g_idx + wr * 8 + 15);

    float* orow = out + (size_t)(wr * 8) * N + n;

    if (g0 == g15) {
        // ---- fast path: one group covers all 16 k-rows ----
        const unsigned zw = (unsigned)__ldg(qzeros + g0 * NW + nz);
        const float fz0 = nib2f(zw, zsh + 0);
        const float fz1 = nib2f(zw, zsh + 4);
        const float fz2 = nib2f(zw, zsh + 8);
        const float fz3 = nib2f(zw, zsh + 12);
        const float4 sc = *reinterpret_cast<const float4*>(
                              scales + (size_t)g0 * N + n);

#pragma unroll
        for (int j = 0; j < 8; j++) {
            const int sh = 4 * j;
            float4 o;
            o.x = sc.x * (nib2f(qwa.x, sh) - fz0);
            o.y = sc.y * (nib2f(qwa.y, sh) - fz1);
            o.z = sc.z * (nib2f(qwa.z, sh) - fz2);
            o.w = sc.w * (nib2f(qwa.w, sh) - fz3);
            __stcs(reinterpret_cast<float4*>(orow + (size_t)j * N), o);
        }
#pragma unroll
        for (int j = 0; j < 8; j++) {
            const int sh = 4 * j;
            float4 o;
            o.x = sc.x * (nib2f(qwb.x, sh) - fz0);
            o.y = sc.y * (nib2f(qwb.y, sh) - fz1);
            o.z = sc.z * (nib2f(qwb.z, sh) - fz2);
            o.w = sc.w * (nib2f(qwb.w, sh) - fz3);
            __stcs(reinterpret_cast<float4*>(orow + (size_t)(8 + j) * N), o);
        }
    } else {
        // ---- rare path: group boundary inside this 16-row span ----
#pragma unroll
        for (int j = 0; j < 16; j++) {
            const int g = __ldg(g_idx + wr * 8 + j);
            const unsigned zw = (unsigned)__ldg(qzeros + g * NW + nz);
            const float fz0 = nib2f(zw, zsh + 0);
            const float fz1 = nib2f(zw, zsh + 4);
            const float fz2 = nib2f(zw, zsh + 8);
            const float fz3 = nib2f(zw, zsh + 12);
            const float4 sc = *reinterpret_cast<const float4*>(
                                  scales + (size_t)g * N + n);
            const uint4 qw = (j < 8) ? qwa : qwb;
            const int sh = 4 * (j & 7);
            float4 o;
            o.x = sc.x * (nib2f(qw.x, sh) - fz0);
            o.y = sc.y * (nib2f(qw.y, sh) - fz1);
            o.z = sc.z * (nib2f(qw.z, sh) - fz2);
            o.w = sc.w * (nib2f(qw.w, sh) - fz3);
            __stcs(reinterpret_cast<float4*>(orow + (size_t)j * N), o);
        }
    }
}

extern "C" void kernel_launch(void* const* d_in, const int* in_sizes, int n_in,
                              void* d_out, int out_size)
{
    const int*   qweight = (const int*)  d_in[0];
    const int*   qzeros  = (const int*)  d_in[1];
    const float* scales  = (const float*)d_in[2];
    const int*   g_idx   = (const int*)  d_in[3];
    float*       out     = (float*)      d_out;

    dim3 block(256);
    dim3 grid((N4 + 255) / 256, WR2);
    dequant_kernel<<<grid, block>>>(qweight, qzeros, scales, g_idx, out);
}